// round 2
// baseline (speedup 1.0000x reference)
#include <cuda_runtime.h>
#include <math.h>

#define B_   4
#define S_   2048
#define T_   256
#define H_   2048
#define NH_  16
#define HD_  128

// ---------------------------------------------------------------------------
// Scratch (device globals; no allocations allowed anywhere).
// Referenced directly from kernels -- no cudaGetSymbolAddress needed.
// ---------------------------------------------------------------------------
__device__ float g_Q[B_ * S_ * H_];     // 64 MB
__device__ float g_K[B_ * T_ * H_];     //  8 MB
__device__ float g_V[B_ * T_ * H_];     //  8 MB
__device__ float g_ctx[B_ * S_ * H_];   // 64 MB
__device__ float g_delta[B_ * S_ * H_]; // 64 MB

// ---------------------------------------------------------------------------
// GEMM: C[m,n] = sum_k A[m,k] * W[n,k] + bias[n]    (A:[M,K], W:[N,K], K=N=2048)
// 128x128 block tile, BK=8, 256 threads, 8x8 per thread.
// ---------------------------------------------------------------------------
__global__ __launch_bounds__(256) void sgemm_nt_bias(
    const float* __restrict__ A, const float* __restrict__ W,
    const float* __restrict__ bias, float* __restrict__ C, int M)
{
    const int K = H_, N = H_;
    __shared__ __align__(16) float As[8][128];
    __shared__ __align__(16) float Bs[8][128];

    const int tid  = threadIdx.x;
    const int bm   = blockIdx.y * 128;
    const int bn   = blockIdx.x * 128;
    const int lrow = tid >> 1;        // 0..127
    const int lc   = (tid & 1) * 4;   // 0 or 4

    const float* Ap = A + (size_t)(bm + lrow) * K + lc;
    const float* Wp = W + (size_t)(bn + lrow) * K + lc;

    const int ty = tid >> 4;   // 0..15
    const int tx = tid & 15;   // 0..15

    float acc[8][8];
#pragma unroll
    for (int i = 0; i < 8; i++)
#pragma unroll
        for (int j = 0; j < 8; j++) acc[i][j] = 0.f;

    for (int k0 = 0; k0 < K; k0 += 8) {
        float4 av = *reinterpret_cast<const float4*>(Ap + k0);
        float4 wv = *reinterpret_cast<const float4*>(Wp + k0);
        __syncthreads();
        As[lc + 0][lrow] = av.x; As[lc + 1][lrow] = av.y;
        As[lc + 2][lrow] = av.z; As[lc + 3][lrow] = av.w;
        Bs[lc + 0][lrow] = wv.x; Bs[lc + 1][lrow] = wv.y;
        Bs[lc + 2][lrow] = wv.z; Bs[lc + 3][lrow] = wv.w;
        __syncthreads();
#pragma unroll
        for (int kk = 0; kk < 8; kk++) {
            float4 a0 = *reinterpret_cast<const float4*>(&As[kk][ty * 8]);
            float4 a1 = *reinterpret_cast<const float4*>(&As[kk][ty * 8 + 4]);
            float4 b0 = *reinterpret_cast<const float4*>(&Bs[kk][tx * 8]);
            float4 b1 = *reinterpret_cast<const float4*>(&Bs[kk][tx * 8 + 4]);
            float ar[8] = {a0.x, a0.y, a0.z, a0.w, a1.x, a1.y, a1.z, a1.w};
            float br[8] = {b0.x, b0.y, b0.z, b0.w, b1.x, b1.y, b1.z, b1.w};
#pragma unroll
            for (int i = 0; i < 8; i++)
#pragma unroll
                for (int j = 0; j < 8; j++)
                    acc[i][j] += ar[i] * br[j];
        }
    }

#pragma unroll
    for (int i = 0; i < 8; i++) {
        const int row = bm + ty * 8 + i;
        float* Cp = C + (size_t)row * N + bn + tx * 8;
#pragma unroll
        for (int j = 0; j < 8; j++)
            Cp[j] = acc[i][j] + bias[bn + tx * 8 + j];
    }
}

// ---------------------------------------------------------------------------
// Attention: one block = one (b,h) x 64 query rows; full T=256 keys.
// threads = dim3(32, 8). Phase 1: scores 64x256 (8x8/thread), row softmax
// via warp shuffles. Phase 2: ctx 64x128 from probs (smem) @ V tiles.
// Dynamic smem (floats): As[16*64] @0, Ks[16*256] @1024, Ps[64*260] @5120.
// Vs[32*128] reuses @0.
// ---------------------------------------------------------------------------
#define PS_STRIDE 260
#define ATTN_SMEM_FLOATS (5120 + 64 * PS_STRIDE)
#define ATTN_SMEM_BYTES  (ATTN_SMEM_FLOATS * 4)

__global__ __launch_bounds__(256) void attn_kernel(const int* __restrict__ mask)
{
    extern __shared__ __align__(16) float sm[];
    float* As = sm;            // [16][64]
    float* Ks = sm + 1024;     // [16][256]
    float* Ps = sm + 5120;     // [64][PS_STRIDE]
    float* Vs = sm;            // [32][128] (reuses As/Ks space)

    const int tx  = threadIdx.x;          // 0..31 (lane)
    const int ty  = threadIdx.y;          // 0..7
    const int tid = ty * 32 + tx;
    const int b   = blockIdx.y >> 4;
    const int h   = blockIdx.y & 15;
    const int s0  = blockIdx.x * 64;

    const float* Qb = g_Q + (size_t)(b * S_ + s0) * H_ + h * HD_;
    const float* Kb = g_K + (size_t)b * T_ * H_ + h * HD_;
    const float* Vb = g_V + (size_t)b * T_ * H_ + h * HD_;

    bool am[8];
#pragma unroll
    for (int j = 0; j < 8; j++) am[j] = mask[b * T_ + tx * 8 + j] > 0;

    float acc[8][8];
#pragma unroll
    for (int i = 0; i < 8; i++)
#pragma unroll
        for (int j = 0; j < 8; j++) acc[i][j] = 0.f;

    const int qrow = tid >> 2;          // 0..63
    const int qc   = (tid & 3) * 4;     // 0,4,8,12

    // ---- Phase 1: scores = Q @ K^T over d-chunks of 16 ----
    for (int kc = 0; kc < 8; kc++) {
        const int d0 = kc * 16;
        float4 qv = *reinterpret_cast<const float4*>(Qb + (size_t)qrow * H_ + d0 + qc);
        float4 kv[4];
#pragma unroll
        for (int r = 0; r < 4; r++) {
            const int t = (tid >> 2) + 64 * r;
            kv[r] = *reinterpret_cast<const float4*>(Kb + (size_t)t * H_ + d0 + qc);
        }
        __syncthreads();
        As[(qc + 0) * 64 + qrow] = qv.x;
        As[(qc + 1) * 64 + qrow] = qv.y;
        As[(qc + 2) * 64 + qrow] = qv.z;
        As[(qc + 3) * 64 + qrow] = qv.w;
#pragma unroll
        for (int r = 0; r < 4; r++) {
            const int t = (tid >> 2) + 64 * r;
            Ks[(qc + 0) * 256 + t] = kv[r].x;
            Ks[(qc + 1) * 256 + t] = kv[r].y;
            Ks[(qc + 2) * 256 + t] = kv[r].z;
            Ks[(qc + 3) * 256 + t] = kv[r].w;
        }
        __syncthreads();
#pragma unroll
        for (int dd = 0; dd < 16; dd++) {
            float4 a0 = *reinterpret_cast<const float4*>(&As[dd * 64 + ty * 8]);
            float4 a1 = *reinterpret_cast<const float4*>(&As[dd * 64 + ty * 8 + 4]);
            float4 b0 = *reinterpret_cast<const float4*>(&Ks[dd * 256 + tx * 8]);
            float4 b1 = *reinterpret_cast<const float4*>(&Ks[dd * 256 + tx * 8 + 4]);
            float ar[8] = {a0.x, a0.y, a0.z, a0.w, a1.x, a1.y, a1.z, a1.w};
            float br[8] = {b0.x, b0.y, b0.z, b0.w, b1.x, b1.y, b1.z, b1.w};
#pragma unroll
            for (int i = 0; i < 8; i++)
#pragma unroll
                for (int j = 0; j < 8; j++)
                    acc[i][j] += ar[i] * br[j];
        }
    }

    // ---- scale / clip / mask + row softmax ----
    const float scale = 0.08838834764831845f;  // 1/sqrt(128)
#pragma unroll
    for (int i = 0; i < 8; i++) {
        float mx = -60.f;
#pragma unroll
        for (int j = 0; j < 8; j++) {
            float s = acc[i][j] * scale;
            s = fminf(fmaxf(s, -50.f), 50.f);
            if (!am[j]) s = -50.f;   // where(attend, s, -10000) then clip -> -50
            acc[i][j] = s;
            mx = fmaxf(mx, s);
        }
#pragma unroll
        for (int o = 16; o; o >>= 1) mx = fmaxf(mx, __shfl_xor_sync(0xffffffffu, mx, o));
        float se = 0.f;
#pragma unroll
        for (int j = 0; j < 8; j++) { acc[i][j] = __expf(acc[i][j] - mx); se += acc[i][j]; }
#pragma unroll
        for (int o = 16; o; o >>= 1) se += __shfl_xor_sync(0xffffffffu, se, o);
        const float inv = 1.f / se;
#pragma unroll
        for (int j = 0; j < 8; j++)
            Ps[(ty * 8 + i) * PS_STRIDE + tx * 8 + j] = acc[i][j] * inv;
    }
    __syncthreads();

    // ---- Phase 2: ctx = probs @ V over t-chunks of 32 ----
    float c2[8][4];
#pragma unroll
    for (int i = 0; i < 8; i++)
#pragma unroll
        for (int j = 0; j < 4; j++) c2[i][j] = 0.f;

    for (int tc = 0; tc < 8; tc++) {
        const int t0 = tc * 32;
        float4 vv[4];
#pragma unroll
        for (int r = 0; r < 4; r++) {
            const int idx = tid + r * 256;
            const int vr = idx >> 5;          // 0..31
            const int vc = (idx & 31) * 4;    // 0..124
            vv[r] = *reinterpret_cast<const float4*>(Vb + (size_t)(t0 + vr) * H_ + vc);
        }
        __syncthreads();
#pragma unroll
        for (int r = 0; r < 4; r++) {
            const int idx = tid + r * 256;
            const int vr = idx >> 5;
            const int vc = (idx & 31) * 4;
            *reinterpret_cast<float4*>(&Vs[vr * 128 + vc]) = vv[r];
        }
        __syncthreads();
#pragma unroll
        for (int tt = 0; tt < 32; tt++) {
            float4 v = *reinterpret_cast<const float4*>(&Vs[tt * 128 + tx * 4]);
#pragma unroll
            for (int i = 0; i < 8; i++) {
                const float p = Ps[(ty * 8 + i) * PS_STRIDE + t0 + tt];
                c2[i][0] += p * v.x;
                c2[i][1] += p * v.y;
                c2[i][2] += p * v.z;
                c2[i][3] += p * v.w;
            }
        }
    }

#pragma unroll
    for (int i = 0; i < 8; i++) {
        float* o = g_ctx + (size_t)(b * S_ + s0 + ty * 8 + i) * H_ + h * HD_ + tx * 4;
        float4 w = make_float4(c2[i][0], c2[i][1], c2[i][2], c2[i][3]);
        *reinterpret_cast<float4*>(o) = w;
    }
}

// ---------------------------------------------------------------------------
// LayerNorm: out = ((rs*d) - mu) / sqrt(var + 1e-5) * gamma + beta
// One block (256 threads) per row of 2048. Biased variance.
// ---------------------------------------------------------------------------
__device__ __forceinline__ float block_sum256(float val, float* red)
{
#pragma unroll
    for (int o = 16; o; o >>= 1) val += __shfl_xor_sync(0xffffffffu, val, o);
    if ((threadIdx.x & 31) == 0) red[threadIdx.x >> 5] = val;
    __syncthreads();
    float tot = red[0] + red[1] + red[2] + red[3] + red[4] + red[5] + red[6] + red[7];
    __syncthreads();
    return tot;
}

__global__ __launch_bounds__(256) void ln_kernel(
    const float* __restrict__ rsp,
    const float* __restrict__ gamma, const float* __restrict__ beta,
    float* __restrict__ out)
{
    __shared__ float red[8];
    const int row = blockIdx.x;
    const int tid = threadIdx.x;
    const float rs = fminf(fmaxf(rsp[0], 0.f), 0.3f);
    const float* x = g_delta + (size_t)row * H_;

    float v[8];
    float s = 0.f;
#pragma unroll
    for (int k = 0; k < 8; k++) { v[k] = rs * x[tid + 256 * k]; s += v[k]; }
    const float mean = block_sum256(s, red) * (1.f / H_);

    float sq = 0.f;
#pragma unroll
    for (int k = 0; k < 8; k++) { float d = v[k] - mean; sq += d * d; }
    const float var = block_sum256(sq, red) * (1.f / H_);
    const float inv = rsqrtf(var + 1e-5f);

#pragma unroll
    for (int k = 0; k < 8; k++) {
        const int c = tid + 256 * k;
        out[(size_t)row * H_ + c] = (v[k] - mean) * inv * gamma[c] + beta[c];
    }
}

// ---------------------------------------------------------------------------
// Small device-global pointer shims so GEMM kernels can write scratch without
// host-side symbol lookups: we pass nullptr and select inside? No -- simpler:
// dedicated wrappers that write directly to the device globals.
// ---------------------------------------------------------------------------
__global__ __launch_bounds__(256) void sgemm_q(const float* __restrict__ A,
                                               const float* __restrict__ W,
                                               const float* __restrict__ bias) {
    // forward to generic path via direct global
    // (thin wrappers keep sgemm_nt_bias generic without symbol lookups)
}

extern "C" void kernel_launch(void* const* d_in, const int* in_sizes, int n_in,
                              void* d_out, int out_size)
{
    const float* hs    = (const float*)d_in[0];
    const float* at    = (const float*)d_in[1];
    const int*   mask  = (const int*)  d_in[2];
    const float* Wq    = (const float*)d_in[3];
    const float* bq    = (const float*)d_in[4];
    const float* Wk    = (const float*)d_in[5];
    const float* bk    = (const float*)d_in[6];
    const float* Wv    = (const float*)d_in[7];
    const float* bv    = (const float*)d_in[8];
    const float* Wo    = (const float*)d_in[9];
    const float* bo    = (const float*)d_in[10];
    const float* gamma = (const float*)d_in[11];
    const float* beta  = (const float*)d_in[12];
    const float* rsp   = (const float*)d_in[13];
    float* out = (float*)d_out;

    // Resolve device-global scratch addresses (host API, idempotent,
    // graph-capture legal: not a stream operation).
    float *Qp = nullptr, *Kp = nullptr, *Vp = nullptr, *Cp = nullptr, *Dp = nullptr;
    cudaGetSymbolAddress((void**)&Qp, g_Q);
    cudaGetSymbolAddress((void**)&Kp, g_K);
    cudaGetSymbolAddress((void**)&Vp, g_V);
    cudaGetSymbolAddress((void**)&Cp, g_ctx);
    cudaGetSymbolAddress((void**)&Dp, g_delta);

    cudaFuncSetAttribute(attn_kernel, cudaFuncAttributeMaxDynamicSharedMemorySize,
                         ATTN_SMEM_BYTES);

    // Q/K/V projections
    {
        dim3 gq(H_ / 128, (B_ * S_) / 128);   // (16, 64)
        sgemm_nt_bias<<<gq, 256>>>(hs, Wq, bq, Qp, B_ * S_);
        dim3 gk(H_ / 128, (B_ * T_) / 128);   // (16, 8)
        sgemm_nt_bias<<<gk, 256>>>(at, Wk, bk, Kp, B_ * T_);
        sgemm_nt_bias<<<gk, 256>>>(at, Wv, bv, Vp, B_ * T_);
    }

    // Attention
    {
        dim3 grid(S_ / 64, B_ * NH_);         // (32, 64)
        dim3 block(32, 8);
        attn_kernel<<<grid, block, ATTN_SMEM_BYTES>>>(mask);
    }

    // Output projection
    {
        dim3 go(H_ / 128, (B_ * S_) / 128);
        sgemm_nt_bias<<<go, 256>>>(Cp, Wo, bo, Dp, B_ * S_);
    }

    // Scale + LayerNorm -> output
    ln_kernel<<<B_ * S_, 256>>>(rsp, gamma, beta, out);
}

// round 4
// speedup vs baseline: 2.0619x; 2.0619x over previous
#include <cuda_runtime.h>
#include <cuda_bf16.h>
#include <math.h>

#define B_   4
#define S_   2048
#define T_   256
#define H_   2048
#define NH_  16
#define HD_  128

// ---------------------------------------------------------------------------
// Scratch (device globals; no allocations allowed anywhere)
// Buffer reuse to minimize footprint:
//   g_Q   : Q output, then reused as O-projection output (delta)
//   g_hsh/g_hsl : hidden_states split, then reused as ctx split
// ---------------------------------------------------------------------------
__device__ float g_Q[B_ * S_ * H_];     // 64 MB (Q, then delta)
__device__ float g_K[B_ * T_ * H_];     //  8 MB
__device__ float g_V[B_ * T_ * H_];     //  8 MB
__device__ float g_ctx[B_ * S_ * H_];   // 64 MB

__device__ __nv_bfloat16 g_hsh[B_ * S_ * H_], g_hsl[B_ * S_ * H_];  // 32+32 MB (hs, then ctx)
__device__ __nv_bfloat16 g_ath[B_ * T_ * H_], g_atl[B_ * T_ * H_];  //  4+4 MB
__device__ __nv_bfloat16 g_wqh[H_ * H_], g_wql[H_ * H_];
__device__ __nv_bfloat16 g_wkh[H_ * H_], g_wkl[H_ * H_];
__device__ __nv_bfloat16 g_wvh[H_ * H_], g_wvl[H_ * H_];
__device__ __nv_bfloat16 g_woh[H_ * H_], g_wol[H_ * H_];

// ---------------------------------------------------------------------------
// Split fp32 -> bf16 hi + bf16 lo  (a ≈ hi + lo, lo = bf16(a - float(hi)))
// ---------------------------------------------------------------------------
__global__ __launch_bounds__(256) void split_kernel(
    const float* __restrict__ x, __nv_bfloat16* __restrict__ hi,
    __nv_bfloat16* __restrict__ lo, int n4)
{
    int i = blockIdx.x * 256 + threadIdx.x;
    if (i >= n4) return;
    float4 v = reinterpret_cast<const float4*>(x)[i];
    __nv_bfloat16 h0 = __float2bfloat16(v.x);
    __nv_bfloat16 h1 = __float2bfloat16(v.y);
    __nv_bfloat16 h2 = __float2bfloat16(v.z);
    __nv_bfloat16 h3 = __float2bfloat16(v.w);
    __nv_bfloat162 H0 = {h0, h1}, H1 = {h2, h3};
    __nv_bfloat162 L0 = {__float2bfloat16(v.x - __bfloat162float(h0)),
                         __float2bfloat16(v.y - __bfloat162float(h1))};
    __nv_bfloat162 L1 = {__float2bfloat16(v.z - __bfloat162float(h2)),
                         __float2bfloat16(v.w - __bfloat162float(h3))};
    reinterpret_cast<__nv_bfloat162*>(hi)[i * 2]     = H0;
    reinterpret_cast<__nv_bfloat162*>(hi)[i * 2 + 1] = H1;
    reinterpret_cast<__nv_bfloat162*>(lo)[i * 2]     = L0;
    reinterpret_cast<__nv_bfloat162*>(lo)[i * 2 + 1] = L1;
}

// ---------------------------------------------------------------------------
// Tensor-core GEMM, bf16 x3-term compensated:
//   C[m,n] = sum_k (Ah+Al)[m,k] * (Wh+Wl)[n,k] + bias[n]   (fp32 accumulate)
// 128x128 block tile, BK=32, 256 threads (8 warps, 64x32 warp tiles).
// Double-buffered smem, register prefetch, one barrier per K-iter.
// Smem rows have stride 40 bf16 (80B) -> conflict-free frag LDS pattern.
// ---------------------------------------------------------------------------
#define GK      H_
#define BKq     32
#define ASTR    40
#define STAGE_E (4 * 128 * ASTR)          // bf16 elems per stage (4 arrays)
#define GEMM_SMEM_BYTES (2 * STAGE_E * 2) // 81920 B

#define MMA16816(d, a, b)                                                   \
    asm volatile(                                                           \
        "mma.sync.aligned.m16n8k16.row.col.f32.bf16.bf16.f32 "              \
        "{%0,%1,%2,%3}, {%4,%5,%6,%7}, {%8,%9}, {%0,%1,%2,%3};"             \
        : "+f"((d)[0]), "+f"((d)[1]), "+f"((d)[2]), "+f"((d)[3])            \
        : "r"((a)[0]), "r"((a)[1]), "r"((a)[2]), "r"((a)[3]),               \
          "r"((b)[0]), "r"((b)[1]))

__global__ __launch_bounds__(256) void gemm_bf16x3_nt_bias(
    const __nv_bfloat16* __restrict__ Ah, const __nv_bfloat16* __restrict__ Al,
    const __nv_bfloat16* __restrict__ Wh, const __nv_bfloat16* __restrict__ Wl,
    const float* __restrict__ bias, float* __restrict__ C)
{
    extern __shared__ __align__(16) __nv_bfloat16 sm[];

    const int tid  = threadIdx.x;
    const int lane = tid & 31;
    const int wid  = tid >> 5;
    const int g    = lane >> 2;       // 0..7
    const int tg   = lane & 3;        // 0..3
    const int wm   = (wid >> 2) * 64; // 0 / 64
    const int wn   = (wid & 3) * 32;  // 0,32,64,96
    const int bm   = blockIdx.y * 128;
    const int bn   = blockIdx.x * 128;

    // G->S chunk mapping: 512 chunks of 8 bf16 (16B); 2 per thread.
    int soff[2]; size_t gA[2], gB[2];
#pragma unroll
    for (int j = 0; j < 2; j++) {
        const int c  = tid + 256 * j;
        const int r  = c >> 2;
        const int cc = c & 3;
        soff[j] = r * ASTR + cc * 8;
        gA[j] = (size_t)(bm + r) * GK + cc * 8;
        gB[j] = (size_t)(bn + r) * GK + cc * 8;
    }

    float acc[4][4][4];
#pragma unroll
    for (int mi = 0; mi < 4; mi++)
#pragma unroll
        for (int ni = 0; ni < 4; ni++)
#pragma unroll
            for (int r = 0; r < 4; r++) acc[mi][ni][r] = 0.f;

    uint4 pAh[2], pAl[2], pBh[2], pBl[2];
#pragma unroll
    for (int j = 0; j < 2; j++) {
        pAh[j] = *reinterpret_cast<const uint4*>(Ah + gA[j]);
        pAl[j] = *reinterpret_cast<const uint4*>(Al + gA[j]);
        pBh[j] = *reinterpret_cast<const uint4*>(Wh + gB[j]);
        pBl[j] = *reinterpret_cast<const uint4*>(Wl + gB[j]);
    }

    const int NIT = GK / BKq;  // 64
    for (int it = 0; it < NIT; it++) {
        __nv_bfloat16* S   = sm + (it & 1) * STAGE_E;
        __nv_bfloat16* SAh = S;
        __nv_bfloat16* SAl = S + 128 * ASTR;
        __nv_bfloat16* SBh = S + 2 * 128 * ASTR;
        __nv_bfloat16* SBl = S + 3 * 128 * ASTR;

#pragma unroll
        for (int j = 0; j < 2; j++) {
            *reinterpret_cast<uint4*>(SAh + soff[j]) = pAh[j];
            *reinterpret_cast<uint4*>(SAl + soff[j]) = pAl[j];
            *reinterpret_cast<uint4*>(SBh + soff[j]) = pBh[j];
            *reinterpret_cast<uint4*>(SBl + soff[j]) = pBl[j];
        }
        __syncthreads();

        if (it + 1 < NIT) {
            const int k0 = (it + 1) * BKq;
#pragma unroll
            for (int j = 0; j < 2; j++) {
                pAh[j] = *reinterpret_cast<const uint4*>(Ah + gA[j] + k0);
                pAl[j] = *reinterpret_cast<const uint4*>(Al + gA[j] + k0);
                pBh[j] = *reinterpret_cast<const uint4*>(Wh + gB[j] + k0);
                pBl[j] = *reinterpret_cast<const uint4*>(Wl + gB[j] + k0);
            }
        }

#pragma unroll
        for (int ks = 0; ks < BKq; ks += 16) {
            unsigned fa_h[4][4], fa_l[4][4], fb_h[4][2], fb_l[4][2];
#pragma unroll
            for (int mi = 0; mi < 4; mi++) {
                const int r0 = wm + mi * 16 + g;
                const int c0 = ks + 2 * tg;
                fa_h[mi][0] = *reinterpret_cast<const unsigned*>(&SAh[r0 * ASTR + c0]);
                fa_h[mi][1] = *reinterpret_cast<const unsigned*>(&SAh[(r0 + 8) * ASTR + c0]);
                fa_h[mi][2] = *reinterpret_cast<const unsigned*>(&SAh[r0 * ASTR + c0 + 8]);
                fa_h[mi][3] = *reinterpret_cast<const unsigned*>(&SAh[(r0 + 8) * ASTR + c0 + 8]);
                fa_l[mi][0] = *reinterpret_cast<const unsigned*>(&SAl[r0 * ASTR + c0]);
                fa_l[mi][1] = *reinterpret_cast<const unsigned*>(&SAl[(r0 + 8) * ASTR + c0]);
                fa_l[mi][2] = *reinterpret_cast<const unsigned*>(&SAl[r0 * ASTR + c0 + 8]);
                fa_l[mi][3] = *reinterpret_cast<const unsigned*>(&SAl[(r0 + 8) * ASTR + c0 + 8]);
            }
#pragma unroll
            for (int ni = 0; ni < 4; ni++) {
                const int n0 = wn + ni * 8 + g;
                const int c0 = ks + 2 * tg;
                fb_h[ni][0] = *reinterpret_cast<const unsigned*>(&SBh[n0 * ASTR + c0]);
                fb_h[ni][1] = *reinterpret_cast<const unsigned*>(&SBh[n0 * ASTR + c0 + 8]);
                fb_l[ni][0] = *reinterpret_cast<const unsigned*>(&SBl[n0 * ASTR + c0]);
                fb_l[ni][1] = *reinterpret_cast<const unsigned*>(&SBl[n0 * ASTR + c0 + 8]);
            }
#pragma unroll
            for (int mi = 0; mi < 4; mi++)
#pragma unroll
                for (int ni = 0; ni < 4; ni++) {
                    MMA16816(acc[mi][ni], fa_h[mi], fb_h[ni]);
                    MMA16816(acc[mi][ni], fa_h[mi], fb_l[ni]);
                    MMA16816(acc[mi][ni], fa_l[mi], fb_h[ni]);
                }
        }
        __syncthreads();
    }

    // Epilogue: bias add, fp32 stores
#pragma unroll
    for (int mi = 0; mi < 4; mi++) {
        const int r0 = bm + wm + mi * 16 + g;
#pragma unroll
        for (int ni = 0; ni < 4; ni++) {
            const int c0 = bn + wn + ni * 8 + 2 * tg;
            const float b0 = bias[c0], b1 = bias[c0 + 1];
            float2 v0 = make_float2(acc[mi][ni][0] + b0, acc[mi][ni][1] + b1);
            float2 v1 = make_float2(acc[mi][ni][2] + b0, acc[mi][ni][3] + b1);
            *reinterpret_cast<float2*>(C + (size_t)r0 * H_ + c0)       = v0;
            *reinterpret_cast<float2*>(C + (size_t)(r0 + 8) * H_ + c0) = v1;
        }
    }
}

// ---------------------------------------------------------------------------
// Attention (unchanged from passing R2 kernel)
// ---------------------------------------------------------------------------
#define PS_STRIDE 260
#define ATTN_SMEM_FLOATS (5120 + 64 * PS_STRIDE)
#define ATTN_SMEM_BYTES  (ATTN_SMEM_FLOATS * 4)

__global__ __launch_bounds__(256) void attn_kernel(const int* __restrict__ mask)
{
    extern __shared__ __align__(16) float smf[];
    float* As = smf;            // [16][64]
    float* Ks = smf + 1024;     // [16][256]
    float* Ps = smf + 5120;     // [64][PS_STRIDE]
    float* Vs = smf;            // [32][128] (reuses As/Ks space)

    const int tx  = threadIdx.x;
    const int ty  = threadIdx.y;
    const int tid = ty * 32 + tx;
    const int b   = blockIdx.y >> 4;
    const int h   = blockIdx.y & 15;
    const int s0  = blockIdx.x * 64;

    const float* Qb = g_Q + (size_t)(b * S_ + s0) * H_ + h * HD_;
    const float* Kb = g_K + (size_t)b * T_ * H_ + h * HD_;
    const float* Vb = g_V + (size_t)b * T_ * H_ + h * HD_;

    bool am[8];
#pragma unroll
    for (int j = 0; j < 8; j++) am[j] = mask[b * T_ + tx * 8 + j] > 0;

    float acc[8][8];
#pragma unroll
    for (int i = 0; i < 8; i++)
#pragma unroll
        for (int j = 0; j < 8; j++) acc[i][j] = 0.f;

    const int qrow = tid >> 2;
    const int qc   = (tid & 3) * 4;

    for (int kc = 0; kc < 8; kc++) {
        const int d0 = kc * 16;
        float4 qv = *reinterpret_cast<const float4*>(Qb + (size_t)qrow * H_ + d0 + qc);
        float4 kv[4];
#pragma unroll
        for (int r = 0; r < 4; r++) {
            const int t = (tid >> 2) + 64 * r;
            kv[r] = *reinterpret_cast<const float4*>(Kb + (size_t)t * H_ + d0 + qc);
        }
        __syncthreads();
        As[(qc + 0) * 64 + qrow] = qv.x;
        As[(qc + 1) * 64 + qrow] = qv.y;
        As[(qc + 2) * 64 + qrow] = qv.z;
        As[(qc + 3) * 64 + qrow] = qv.w;
#pragma unroll
        for (int r = 0; r < 4; r++) {
            const int t = (tid >> 2) + 64 * r;
            Ks[(qc + 0) * 256 + t] = kv[r].x;
            Ks[(qc + 1) * 256 + t] = kv[r].y;
            Ks[(qc + 2) * 256 + t] = kv[r].z;
            Ks[(qc + 3) * 256 + t] = kv[r].w;
        }
        __syncthreads();
#pragma unroll
        for (int dd = 0; dd < 16; dd++) {
            float4 a0 = *reinterpret_cast<const float4*>(&As[dd * 64 + ty * 8]);
            float4 a1 = *reinterpret_cast<const float4*>(&As[dd * 64 + ty * 8 + 4]);
            float4 b0 = *reinterpret_cast<const float4*>(&Ks[dd * 256 + tx * 8]);
            float4 b1 = *reinterpret_cast<const float4*>(&Ks[dd * 256 + tx * 8 + 4]);
            float ar[8] = {a0.x, a0.y, a0.z, a0.w, a1.x, a1.y, a1.z, a1.w};
            float br[8] = {b0.x, b0.y, b0.z, b0.w, b1.x, b1.y, b1.z, b1.w};
#pragma unroll
            for (int i = 0; i < 8; i++)
#pragma unroll
                for (int j = 0; j < 8; j++)
                    acc[i][j] += ar[i] * br[j];
        }
    }

    const float scale = 0.08838834764831845f;
#pragma unroll
    for (int i = 0; i < 8; i++) {
        float mx = -60.f;
#pragma unroll
        for (int j = 0; j < 8; j++) {
            float s = acc[i][j] * scale;
            s = fminf(fmaxf(s, -50.f), 50.f);
            if (!am[j]) s = -50.f;
            acc[i][j] = s;
            mx = fmaxf(mx, s);
        }
#pragma unroll
        for (int o = 16; o; o >>= 1) mx = fmaxf(mx, __shfl_xor_sync(0xffffffffu, mx, o));
        float se = 0.f;
#pragma unroll
        for (int j = 0; j < 8; j++) { acc[i][j] = __expf(acc[i][j] - mx); se += acc[i][j]; }
#pragma unroll
        for (int o = 16; o; o >>= 1) se += __shfl_xor_sync(0xffffffffu, se, o);
        const float inv = 1.f / se;
#pragma unroll
        for (int j = 0; j < 8; j++)
            Ps[(ty * 8 + i) * PS_STRIDE + tx * 8 + j] = acc[i][j] * inv;
    }
    __syncthreads();

    float c2[8][4];
#pragma unroll
    for (int i = 0; i < 8; i++)
#pragma unroll
        for (int j = 0; j < 4; j++) c2[i][j] = 0.f;

    for (int tc = 0; tc < 8; tc++) {
        const int t0 = tc * 32;
        float4 vv[4];
#pragma unroll
        for (int r = 0; r < 4; r++) {
            const int idx = tid + r * 256;
            const int vr = idx >> 5;
            const int vc = (idx & 31) * 4;
            vv[r] = *reinterpret_cast<const float4*>(Vb + (size_t)(t0 + vr) * H_ + vc);
        }
        __syncthreads();
#pragma unroll
        for (int r = 0; r < 4; r++) {
            const int idx = tid + r * 256;
            const int vr = idx >> 5;
            const int vc = (idx & 31) * 4;
            *reinterpret_cast<float4*>(&Vs[vr * 128 + vc]) = vv[r];
        }
        __syncthreads();
#pragma unroll
        for (int tt = 0; tt < 32; tt++) {
            float4 v = *reinterpret_cast<const float4*>(&Vs[tt * 128 + tx * 4]);
#pragma unroll
            for (int i = 0; i < 8; i++) {
                const float p = Ps[(ty * 8 + i) * PS_STRIDE + t0 + tt];
                c2[i][0] += p * v.x;
                c2[i][1] += p * v.y;
                c2[i][2] += p * v.z;
                c2[i][3] += p * v.w;
            }
        }
    }

#pragma unroll
    for (int i = 0; i < 8; i++) {
        float* o = g_ctx + (size_t)(b * S_ + s0 + ty * 8 + i) * H_ + h * HD_ + tx * 4;
        float4 w = make_float4(c2[i][0], c2[i][1], c2[i][2], c2[i][3]);
        *reinterpret_cast<float4*>(o) = w;
    }
}

// ---------------------------------------------------------------------------
// LayerNorm: out = ((rs*d) - mu) / sqrt(var + 1e-5) * gamma + beta
// ---------------------------------------------------------------------------
__device__ __forceinline__ float block_sum256(float val, float* red)
{
#pragma unroll
    for (int o = 16; o; o >>= 1) val += __shfl_xor_sync(0xffffffffu, val, o);
    if ((threadIdx.x & 31) == 0) red[threadIdx.x >> 5] = val;
    __syncthreads();
    float tot = red[0] + red[1] + red[2] + red[3] + red[4] + red[5] + red[6] + red[7];
    __syncthreads();
    return tot;
}

__global__ __launch_bounds__(256) void ln_kernel(
    const float* __restrict__ delta, const float* __restrict__ rsp,
    const float* __restrict__ gamma, const float* __restrict__ beta,
    float* __restrict__ out)
{
    __shared__ float red[8];
    const int row = blockIdx.x;
    const int tid = threadIdx.x;
    const float rs = fminf(fmaxf(rsp[0], 0.f), 0.3f);
    const float* x = delta + (size_t)row * H_;

    float v[8];
    float s = 0.f;
#pragma unroll
    for (int k = 0; k < 8; k++) { v[k] = rs * x[tid + 256 * k]; s += v[k]; }
    const float mean = block_sum256(s, red) * (1.f / H_);

    float sq = 0.f;
#pragma unroll
    for (int k = 0; k < 8; k++) { float d = v[k] - mean; sq += d * d; }
    const float var = block_sum256(sq, red) * (1.f / H_);
    const float inv = rsqrtf(var + 1e-5f);

#pragma unroll
    for (int k = 0; k < 8; k++) {
        const int c = tid + 256 * k;
        out[(size_t)row * H_ + c] = (v[k] - mean) * inv * gamma[c] + beta[c];
    }
}

// ---------------------------------------------------------------------------
// Launch
// ---------------------------------------------------------------------------
extern "C" void kernel_launch(void* const* d_in, const int* in_sizes, int n_in,
                              void* d_out, int out_size)
{
    const float* hs    = (const float*)d_in[0];
    const float* at    = (const float*)d_in[1];
    const int*   mask  = (const int*)  d_in[2];
    const float* Wq    = (const float*)d_in[3];
    const float* bq    = (const float*)d_in[4];
    const float* Wk    = (const float*)d_in[5];
    const float* bk    = (const float*)d_in[6];
    const float* Wv    = (const float*)d_in[7];
    const float* bv    = (const float*)d_in[8];
    const float* Wo    = (const float*)d_in[9];
    const float* bo    = (const float*)d_in[10];
    const float* gamma = (const float*)d_in[11];
    const float* beta  = (const float*)d_in[12];
    const float* rsp   = (const float*)d_in[13];
    float* out = (float*)d_out;

    float *Qp, *Kp, *Vp, *Cp;
    __nv_bfloat16 *hsh, *hsl, *ath, *atl;
    __nv_bfloat16 *wqh, *wql, *wkh, *wkl, *wvh, *wvl, *woh, *wol;
    cudaGetSymbolAddress((void**)&Qp,  g_Q);
    cudaGetSymbolAddress((void**)&Kp,  g_K);
    cudaGetSymbolAddress((void**)&Vp,  g_V);
    cudaGetSymbolAddress((void**)&Cp,  g_ctx);
    cudaGetSymbolAddress((void**)&hsh, g_hsh); cudaGetSymbolAddress((void**)&hsl, g_hsl);
    cudaGetSymbolAddress((void**)&ath, g_ath); cudaGetSymbolAddress((void**)&atl, g_atl);
    cudaGetSymbolAddress((void**)&wqh, g_wqh); cudaGetSymbolAddress((void**)&wql, g_wql);
    cudaGetSymbolAddress((void**)&wkh, g_wkh); cudaGetSymbolAddress((void**)&wkl, g_wkl);
    cudaGetSymbolAddress((void**)&wvh, g_wvh); cudaGetSymbolAddress((void**)&wvl, g_wvl);
    cudaGetSymbolAddress((void**)&woh, g_woh); cudaGetSymbolAddress((void**)&wol, g_wol);

    cudaFuncSetAttribute(attn_kernel, cudaFuncAttributeMaxDynamicSharedMemorySize,
                         ATTN_SMEM_BYTES);
    cudaFuncSetAttribute(gemm_bf16x3_nt_bias, cudaFuncAttributeMaxDynamicSharedMemorySize,
                         GEMM_SMEM_BYTES);

    // Splits
    const int nHS = B_ * S_ * H_ / 4, nAT = B_ * T_ * H_ / 4, nW = H_ * H_ / 4;
    split_kernel<<<(nHS + 255) / 256, 256>>>(hs, hsh, hsl, nHS);
    split_kernel<<<(nAT + 255) / 256, 256>>>(at, ath, atl, nAT);
    split_kernel<<<(nW + 255) / 256, 256>>>(Wq, wqh, wql, nW);
    split_kernel<<<(nW + 255) / 256, 256>>>(Wk, wkh, wkl, nW);
    split_kernel<<<(nW + 255) / 256, 256>>>(Wv, wvh, wvl, nW);
    split_kernel<<<(nW + 255) / 256, 256>>>(Wo, woh, wol, nW);

    // Q/K/V projections (tensor cores)
    {
        dim3 gq(H_ / 128, (B_ * S_) / 128);   // (16, 64)
        gemm_bf16x3_nt_bias<<<gq, 256, GEMM_SMEM_BYTES>>>(hsh, hsl, wqh, wql, bq, Qp);
        dim3 gk(H_ / 128, (B_ * T_) / 128);   // (16, 8)
        gemm_bf16x3_nt_bias<<<gk, 256, GEMM_SMEM_BYTES>>>(ath, atl, wkh, wkl, bk, Kp);
        gemm_bf16x3_nt_bias<<<gk, 256, GEMM_SMEM_BYTES>>>(ath, atl, wvh, wvl, bv, Vp);
    }

    // Attention (reads g_Q, g_K, g_V -> writes g_ctx)
    {
        dim3 grid(S_ / 64, B_ * NH_);
        dim3 block(32, 8);
        attn_kernel<<<grid, block, ATTN_SMEM_BYTES>>>(mask);
    }

    // Output projection: split ctx (reusing hs split buffers), write delta into g_Q
    split_kernel<<<(nHS + 255) / 256, 256>>>(Cp, hsh, hsl, nHS);
    {
        dim3 go(H_ / 128, (B_ * S_) / 128);
        gemm_bf16x3_nt_bias<<<go, 256, GEMM_SMEM_BYTES>>>(hsh, hsl, woh, wol, bo, Qp);
    }

    // Scale + LayerNorm -> output
    ln_kernel<<<B_ * S_, 256>>>(Qp, rsp, gamma, beta, out);
}

// round 7
// speedup vs baseline: 2.0824x; 1.0099x over previous
#include <cuda_runtime.h>
#include <cuda_bf16.h>
#include <math.h>
#include <stdint.h>

#define B_   4
#define S_   2048
#define T_   256
#define H_   2048
#define NH_  16
#define HD_  128

// ---------------------------------------------------------------------------
// Scratch (device globals; no allocations allowed anywhere)
//   g_Q : Q output, then reused as O-projection output (delta)
//   g_hsh/g_hsl : hidden_states split, then reused as ctx split
// ---------------------------------------------------------------------------
__device__ float g_Q[B_ * S_ * H_];     // 64 MB (Q, then delta)
__device__ float g_K[B_ * T_ * H_];     //  8 MB
__device__ float g_V[B_ * T_ * H_];     //  8 MB
__device__ float g_ctx[B_ * S_ * H_];   // 64 MB

__device__ __nv_bfloat16 g_hsh[B_ * S_ * H_], g_hsl[B_ * S_ * H_];
__device__ __nv_bfloat16 g_ath[B_ * T_ * H_], g_atl[B_ * T_ * H_];
__device__ __nv_bfloat16 g_wqh[H_ * H_], g_wql[H_ * H_];
__device__ __nv_bfloat16 g_wkh[H_ * H_], g_wkl[H_ * H_];
__device__ __nv_bfloat16 g_wvh[H_ * H_], g_wvl[H_ * H_];
__device__ __nv_bfloat16 g_woh[H_ * H_], g_wol[H_ * H_];

// ---------------------------------------------------------------------------
// Split fp32 -> bf16 hi + bf16 lo  (a ≈ hi + lo)
// ---------------------------------------------------------------------------
__global__ __launch_bounds__(256) void split_kernel(
    const float* __restrict__ x, __nv_bfloat16* __restrict__ hi,
    __nv_bfloat16* __restrict__ lo, int n4)
{
    int i = blockIdx.x * 256 + threadIdx.x;
    if (i >= n4) return;
    float4 v = reinterpret_cast<const float4*>(x)[i];
    __nv_bfloat16 h0 = __float2bfloat16(v.x);
    __nv_bfloat16 h1 = __float2bfloat16(v.y);
    __nv_bfloat16 h2 = __float2bfloat16(v.z);
    __nv_bfloat16 h3 = __float2bfloat16(v.w);
    __nv_bfloat162 H0 = {h0, h1}, H1 = {h2, h3};
    __nv_bfloat162 L0 = {__float2bfloat16(v.x - __bfloat162float(h0)),
                         __float2bfloat16(v.y - __bfloat162float(h1))};
    __nv_bfloat162 L1 = {__float2bfloat16(v.z - __bfloat162float(h2)),
                         __float2bfloat16(v.w - __bfloat162float(h3))};
    reinterpret_cast<__nv_bfloat162*>(hi)[i * 2]     = H0;
    reinterpret_cast<__nv_bfloat162*>(hi)[i * 2 + 1] = H1;
    reinterpret_cast<__nv_bfloat162*>(lo)[i * 2]     = L0;
    reinterpret_cast<__nv_bfloat162*>(lo)[i * 2 + 1] = L1;
}

// ---------------------------------------------------------------------------
// Tensor-core GEMM (mma.sync, bf16 3-term compensated), cp.async pipeline:
//   C[m,n] = sum_k (Ah+Al)[m,k]*(Wh+Wl)[n,k] + bias[n], fp32 accumulate.
// 128x128 block tile, BK=32, 256 threads (8 warps, 64x32 warp tiles).
// 3-stage cp.async circular pipeline, one barrier per K-iter.
// Smem rows: 40 bf16 (80B) stride -> conflict-free LDS.32 frag pattern
// (validated in the passing R4 kernel).
// ---------------------------------------------------------------------------
#define GK       H_
#define BKq      32
#define ASTR     40
#define ARR_B    (128 * ASTR * 2)            // 10240 B per array
#define STG_B    (4 * ARR_B)                 // 40960 B per stage
#define NSTAGE   3
#define GEMM_SMEM_BYTES (NSTAGE * STG_B)     // 122880 B

#define CP_ASYNC16(dst, src) \
    asm volatile("cp.async.cg.shared.global [%0], [%1], 16;" \
                 :: "r"(dst), "l"(src) : "memory")
#define CP_COMMIT()  asm volatile("cp.async.commit_group;" ::: "memory")
#define CP_WAIT(N)   asm volatile("cp.async.wait_group %0;" :: "n"(N) : "memory")

#define MMA16816(d, a, b)                                                   \
    asm volatile(                                                           \
        "mma.sync.aligned.m16n8k16.row.col.f32.bf16.bf16.f32 "              \
        "{%0,%1,%2,%3}, {%4,%5,%6,%7}, {%8,%9}, {%0,%1,%2,%3};"             \
        : "+f"((d)[0]), "+f"((d)[1]), "+f"((d)[2]), "+f"((d)[3])            \
        : "r"((a)[0]), "r"((a)[1]), "r"((a)[2]), "r"((a)[3]),               \
          "r"((b)[0]), "r"((b)[1]))

__device__ __forceinline__ uint32_t smem_u32g(const void* p) {
    uint32_t a;
    asm("{ .reg .u64 t; cvta.to.shared.u64 t, %1; cvt.u32.u64 %0, t; }"
        : "=r"(a) : "l"(p));
    return a;
}

__global__ __launch_bounds__(256) void gemm_cp3_nt_bias(
    const __nv_bfloat16* __restrict__ Ah, const __nv_bfloat16* __restrict__ Al,
    const __nv_bfloat16* __restrict__ Wh, const __nv_bfloat16* __restrict__ Wl,
    const float* __restrict__ bias, float* __restrict__ C)
{
    extern __shared__ __align__(16) char smc[];
    const uint32_t sbase = smem_u32g(smc);

    const int tid  = threadIdx.x;
    const int lane = tid & 31;
    const int wid  = tid >> 5;
    const int g    = lane >> 2;       // 0..7
    const int tg   = lane & 3;        // 0..3
    const int wm   = (wid >> 2) * 64; // 0 / 64
    const int wn   = (wid & 3) * 32;  // 0,32,64,96
    const int bm   = blockIdx.y * 128;
    const int bn   = blockIdx.x * 128;

    // Loader mapping: per array 512 chunks of 16B; 2 per thread.
    uint32_t so[2];
    size_t gA[2], gB[2];
#pragma unroll
    for (int j = 0; j < 2; j++) {
        const int c  = tid + 256 * j;
        const int r  = c >> 2;
        const int cc = c & 3;
        so[j] = (uint32_t)(r * 80 + cc * 16);
        gA[j] = (size_t)(bm + r) * GK + cc * 8;
        gB[j] = (size_t)(bn + r) * GK + cc * 8;
    }

    float acc[4][4][4];
#pragma unroll
    for (int mi = 0; mi < 4; mi++)
#pragma unroll
        for (int ni = 0; ni < 4; ni++)
#pragma unroll
            for (int r = 0; r < 4; r++) acc[mi][ni][r] = 0.f;

    const int NIT = GK / BKq;  // 64

    // Issue a full stage of cp.async for K-chunk `kit` into buffer `buf`.
    auto issue_stage = [&](int kit, int buf) {
        const uint32_t sb = sbase + buf * STG_B;
        const int k0 = kit * BKq;
#pragma unroll
        for (int j = 0; j < 2; j++) {
            CP_ASYNC16(sb + so[j],             Ah + gA[j] + k0);
            CP_ASYNC16(sb + ARR_B + so[j],     Al + gA[j] + k0);
            CP_ASYNC16(sb + 2 * ARR_B + so[j], Wh + gB[j] + k0);
            CP_ASYNC16(sb + 3 * ARR_B + so[j], Wl + gB[j] + k0);
        }
        CP_COMMIT();
    };

    issue_stage(0, 0);
    issue_stage(1, 1);

    for (int it = 0; it < NIT; it++) {
        if (it < NIT - 1) { CP_WAIT(1); } else { CP_WAIT(0); }
        __syncthreads();

        if (it + 2 < NIT) issue_stage(it + 2, (it + 2) % NSTAGE);

        const char* S = smc + (it % NSTAGE) * STG_B;
        const __nv_bfloat16* SAh = reinterpret_cast<const __nv_bfloat16*>(S);
        const __nv_bfloat16* SAl = reinterpret_cast<const __nv_bfloat16*>(S + ARR_B);
        const __nv_bfloat16* SBh = reinterpret_cast<const __nv_bfloat16*>(S + 2 * ARR_B);
        const __nv_bfloat16* SBl = reinterpret_cast<const __nv_bfloat16*>(S + 3 * ARR_B);

#pragma unroll
        for (int ks = 0; ks < BKq; ks += 16) {
            unsigned fa_h[4][4], fa_l[4][4], fb_h[4][2], fb_l[4][2];
#pragma unroll
            for (int mi = 0; mi < 4; mi++) {
                const int r0 = wm + mi * 16 + g;
                const int c0 = ks + 2 * tg;
                fa_h[mi][0] = *reinterpret_cast<const unsigned*>(&SAh[r0 * ASTR + c0]);
                fa_h[mi][1] = *reinterpret_cast<const unsigned*>(&SAh[(r0 + 8) * ASTR + c0]);
                fa_h[mi][2] = *reinterpret_cast<const unsigned*>(&SAh[r0 * ASTR + c0 + 8]);
                fa_h[mi][3] = *reinterpret_cast<const unsigned*>(&SAh[(r0 + 8) * ASTR + c0 + 8]);
                fa_l[mi][0] = *reinterpret_cast<const unsigned*>(&SAl[r0 * ASTR + c0]);
                fa_l[mi][1] = *reinterpret_cast<const unsigned*>(&SAl[(r0 + 8) * ASTR + c0]);
                fa_l[mi][2] = *reinterpret_cast<const unsigned*>(&SAl[r0 * ASTR + c0 + 8]);
                fa_l[mi][3] = *reinterpret_cast<const unsigned*>(&SAl[(r0 + 8) * ASTR + c0 + 8]);
            }
#pragma unroll
            for (int ni = 0; ni < 4; ni++) {
                const int n0 = wn + ni * 8 + g;
                const int c0 = ks + 2 * tg;
                fb_h[ni][0] = *reinterpret_cast<const unsigned*>(&SBh[n0 * ASTR + c0]);
                fb_h[ni][1] = *reinterpret_cast<const unsigned*>(&SBh[n0 * ASTR + c0 + 8]);
                fb_l[ni][0] = *reinterpret_cast<const unsigned*>(&SBl[n0 * ASTR + c0]);
                fb_l[ni][1] = *reinterpret_cast<const unsigned*>(&SBl[n0 * ASTR + c0 + 8]);
            }
#pragma unroll
            for (int mi = 0; mi < 4; mi++)
#pragma unroll
                for (int ni = 0; ni < 4; ni++) {
                    MMA16816(acc[mi][ni], fa_h[mi], fb_h[ni]);
                    MMA16816(acc[mi][ni], fa_h[mi], fb_l[ni]);
                    MMA16816(acc[mi][ni], fa_l[mi], fb_h[ni]);
                }
        }
    }

    // Epilogue: bias add, fp32 stores
#pragma unroll
    for (int mi = 0; mi < 4; mi++) {
        const int r0 = bm + wm + mi * 16 + g;
#pragma unroll
        for (int ni = 0; ni < 4; ni++) {
            const int c0 = bn + wn + ni * 8 + 2 * tg;
            const float b0 = bias[c0], b1 = bias[c0 + 1];
            float2 v0 = make_float2(acc[mi][ni][0] + b0, acc[mi][ni][1] + b1);
            float2 v1 = make_float2(acc[mi][ni][2] + b0, acc[mi][ni][3] + b1);
            *reinterpret_cast<float2*>(C + (size_t)r0 * H_ + c0)       = v0;
            *reinterpret_cast<float2*>(C + (size_t)(r0 + 8) * H_ + c0) = v1;
        }
    }
}

// ---------------------------------------------------------------------------
// Attention (unchanged from passing R4 kernel)
// ---------------------------------------------------------------------------
#define PS_STRIDE 260
#define ATTN_SMEM_FLOATS (5120 + 64 * PS_STRIDE)
#define ATTN_SMEM_BYTES  (ATTN_SMEM_FLOATS * 4)

__global__ __launch_bounds__(256) void attn_kernel(const int* __restrict__ mask)
{
    extern __shared__ __align__(16) float smf[];
    float* As = smf;
    float* Ks = smf + 1024;
    float* Ps = smf + 5120;
    float* Vs = smf;

    const int tx  = threadIdx.x;
    const int ty  = threadIdx.y;
    const int tid = ty * 32 + tx;
    const int b   = blockIdx.y >> 4;
    const int h   = blockIdx.y & 15;
    const int s0  = blockIdx.x * 64;

    const float* Qb = g_Q + (size_t)(b * S_ + s0) * H_ + h * HD_;
    const float* Kb = g_K + (size_t)b * T_ * H_ + h * HD_;
    const float* Vb = g_V + (size_t)b * T_ * H_ + h * HD_;

    bool am[8];
#pragma unroll
    for (int j = 0; j < 8; j++) am[j] = mask[b * T_ + tx * 8 + j] > 0;

    float acc[8][8];
#pragma unroll
    for (int i = 0; i < 8; i++)
#pragma unroll
        for (int j = 0; j < 8; j++) acc[i][j] = 0.f;

    const int qrow = tid >> 2;
    const int qc   = (tid & 3) * 4;

    for (int kc = 0; kc < 8; kc++) {
        const int d0 = kc * 16;
        float4 qv = *reinterpret_cast<const float4*>(Qb + (size_t)qrow * H_ + d0 + qc);
        float4 kv[4];
#pragma unroll
        for (int r = 0; r < 4; r++) {
            const int t = (tid >> 2) + 64 * r;
            kv[r] = *reinterpret_cast<const float4*>(Kb + (size_t)t * H_ + d0 + qc);
        }
        __syncthreads();
        As[(qc + 0) * 64 + qrow] = qv.x;
        As[(qc + 1) * 64 + qrow] = qv.y;
        As[(qc + 2) * 64 + qrow] = qv.z;
        As[(qc + 3) * 64 + qrow] = qv.w;
#pragma unroll
        for (int r = 0; r < 4; r++) {
            const int t = (tid >> 2) + 64 * r;
            Ks[(qc + 0) * 256 + t] = kv[r].x;
            Ks[(qc + 1) * 256 + t] = kv[r].y;
            Ks[(qc + 2) * 256 + t] = kv[r].z;
            Ks[(qc + 3) * 256 + t] = kv[r].w;
        }
        __syncthreads();
#pragma unroll
        for (int dd = 0; dd < 16; dd++) {
            float4 a0 = *reinterpret_cast<const float4*>(&As[dd * 64 + ty * 8]);
            float4 a1 = *reinterpret_cast<const float4*>(&As[dd * 64 + ty * 8 + 4]);
            float4 b0 = *reinterpret_cast<const float4*>(&Ks[dd * 256 + tx * 8]);
            float4 b1 = *reinterpret_cast<const float4*>(&Ks[dd * 256 + tx * 8 + 4]);
            float ar[8] = {a0.x, a0.y, a0.z, a0.w, a1.x, a1.y, a1.z, a1.w};
            float br[8] = {b0.x, b0.y, b0.z, b0.w, b1.x, b1.y, b1.z, b1.w};
#pragma unroll
            for (int i = 0; i < 8; i++)
#pragma unroll
                for (int j = 0; j < 8; j++)
                    acc[i][j] += ar[i] * br[j];
        }
    }

    const float scale = 0.08838834764831845f;
#pragma unroll
    for (int i = 0; i < 8; i++) {
        float mx = -60.f;
#pragma unroll
        for (int j = 0; j < 8; j++) {
            float s = acc[i][j] * scale;
            s = fminf(fmaxf(s, -50.f), 50.f);
            if (!am[j]) s = -50.f;
            acc[i][j] = s;
            mx = fmaxf(mx, s);
        }
#pragma unroll
        for (int o = 16; o; o >>= 1) mx = fmaxf(mx, __shfl_xor_sync(0xffffffffu, mx, o));
        float se = 0.f;
#pragma unroll
        for (int j = 0; j < 8; j++) { acc[i][j] = __expf(acc[i][j] - mx); se += acc[i][j]; }
#pragma unroll
        for (int o = 16; o; o >>= 1) se += __shfl_xor_sync(0xffffffffu, se, o);
        const float inv = 1.f / se;
#pragma unroll
        for (int j = 0; j < 8; j++)
            Ps[(ty * 8 + i) * PS_STRIDE + tx * 8 + j] = acc[i][j] * inv;
    }
    __syncthreads();

    float c2[8][4];
#pragma unroll
    for (int i = 0; i < 8; i++)
#pragma unroll
        for (int j = 0; j < 4; j++) c2[i][j] = 0.f;

    for (int tc = 0; tc < 8; tc++) {
        const int t0 = tc * 32;
        float4 vv[4];
#pragma unroll
        for (int r = 0; r < 4; r++) {
            const int idx = tid + r * 256;
            const int vr = idx >> 5;
            const int vc = (idx & 31) * 4;
            vv[r] = *reinterpret_cast<const float4*>(Vb + (size_t)(t0 + vr) * H_ + vc);
        }
        __syncthreads();
#pragma unroll
        for (int r = 0; r < 4; r++) {
            const int idx = tid + r * 256;
            const int vr = idx >> 5;
            const int vc = (idx & 31) * 4;
            *reinterpret_cast<float4*>(&Vs[vr * 128 + vc]) = vv[r];
        }
        __syncthreads();
#pragma unroll
        for (int tt = 0; tt < 32; tt++) {
            float4 v = *reinterpret_cast<const float4*>(&Vs[tt * 128 + tx * 4]);
#pragma unroll
            for (int i = 0; i < 8; i++) {
                const float p = Ps[(ty * 8 + i) * PS_STRIDE + t0 + tt];
                c2[i][0] += p * v.x;
                c2[i][1] += p * v.y;
                c2[i][2] += p * v.z;
                c2[i][3] += p * v.w;
            }
        }
    }

#pragma unroll
    for (int i = 0; i < 8; i++) {
        float* o = g_ctx + (size_t)(b * S_ + s0 + ty * 8 + i) * H_ + h * HD_ + tx * 4;
        float4 w = make_float4(c2[i][0], c2[i][1], c2[i][2], c2[i][3]);
        *reinterpret_cast<float4*>(o) = w;
    }
}

// ---------------------------------------------------------------------------
// LayerNorm (unchanged)
// ---------------------------------------------------------------------------
__device__ __forceinline__ float block_sum256(float val, float* red)
{
#pragma unroll
    for (int o = 16; o; o >>= 1) val += __shfl_xor_sync(0xffffffffu, val, o);
    if ((threadIdx.x & 31) == 0) red[threadIdx.x >> 5] = val;
    __syncthreads();
    float tot = red[0] + red[1] + red[2] + red[3] + red[4] + red[5] + red[6] + red[7];
    __syncthreads();
    return tot;
}

__global__ __launch_bounds__(256) void ln_kernel(
    const float* __restrict__ delta, const float* __restrict__ rsp,
    const float* __restrict__ gamma, const float* __restrict__ beta,
    float* __restrict__ out)
{
    __shared__ float red[8];
    const int row = blockIdx.x;
    const int tid = threadIdx.x;
    const float rs = fminf(fmaxf(rsp[0], 0.f), 0.3f);
    const float* x = delta + (size_t)row * H_;

    float v[8];
    float s = 0.f;
#pragma unroll
    for (int k = 0; k < 8; k++) { v[k] = rs * x[tid + 256 * k]; s += v[k]; }
    const float mean = block_sum256(s, red) * (1.f / H_);

    float sq = 0.f;
#pragma unroll
    for (int k = 0; k < 8; k++) { float d = v[k] - mean; sq += d * d; }
    const float var = block_sum256(sq, red) * (1.f / H_);
    const float inv = rsqrtf(var + 1e-5f);

#pragma unroll
    for (int k = 0; k < 8; k++) {
        const int c = tid + 256 * k;
        out[(size_t)row * H_ + c] = (v[k] - mean) * inv * gamma[c] + beta[c];
    }
}

// ---------------------------------------------------------------------------
// Launch
// ---------------------------------------------------------------------------
extern "C" void kernel_launch(void* const* d_in, const int* in_sizes, int n_in,
                              void* d_out, int out_size)
{
    const float* hs    = (const float*)d_in[0];
    const float* at    = (const float*)d_in[1];
    const int*   mask  = (const int*)  d_in[2];
    const float* Wq    = (const float*)d_in[3];
    const float* bq    = (const float*)d_in[4];
    const float* Wk    = (const float*)d_in[5];
    const float* bk    = (const float*)d_in[6];
    const float* Wv    = (const float*)d_in[7];
    const float* bv    = (const float*)d_in[8];
    const float* Wo    = (const float*)d_in[9];
    const float* bo    = (const float*)d_in[10];
    const float* gamma = (const float*)d_in[11];
    const float* beta  = (const float*)d_in[12];
    const float* rsp   = (const float*)d_in[13];
    float* out = (float*)d_out;

    float *Qp, *Kp, *Vp, *Cp;
    __nv_bfloat16 *hsh, *hsl, *ath, *atl;
    __nv_bfloat16 *wqh, *wql, *wkh, *wkl, *wvh, *wvl, *woh, *wol;
    cudaGetSymbolAddress((void**)&Qp,  g_Q);
    cudaGetSymbolAddress((void**)&Kp,  g_K);
    cudaGetSymbolAddress((void**)&Vp,  g_V);
    cudaGetSymbolAddress((void**)&Cp,  g_ctx);
    cudaGetSymbolAddress((void**)&hsh, g_hsh); cudaGetSymbolAddress((void**)&hsl, g_hsl);
    cudaGetSymbolAddress((void**)&ath, g_ath); cudaGetSymbolAddress((void**)&atl, g_atl);
    cudaGetSymbolAddress((void**)&wqh, g_wqh); cudaGetSymbolAddress((void**)&wql, g_wql);
    cudaGetSymbolAddress((void**)&wkh, g_wkh); cudaGetSymbolAddress((void**)&wkl, g_wkl);
    cudaGetSymbolAddress((void**)&wvh, g_wvh); cudaGetSymbolAddress((void**)&wvl, g_wvl);
    cudaGetSymbolAddress((void**)&woh, g_woh); cudaGetSymbolAddress((void**)&wol, g_wol);

    cudaFuncSetAttribute(attn_kernel, cudaFuncAttributeMaxDynamicSharedMemorySize,
                         ATTN_SMEM_BYTES);
    cudaFuncSetAttribute(gemm_cp3_nt_bias, cudaFuncAttributeMaxDynamicSharedMemorySize,
                         GEMM_SMEM_BYTES);

    // Splits
    const int nHS = B_ * S_ * H_ / 4, nAT = B_ * T_ * H_ / 4, nW = H_ * H_ / 4;
    split_kernel<<<(nHS + 255) / 256, 256>>>(hs, hsh, hsl, nHS);
    split_kernel<<<(nAT + 255) / 256, 256>>>(at, ath, atl, nAT);
    split_kernel<<<(nW + 255) / 256, 256>>>(Wq, wqh, wql, nW);
    split_kernel<<<(nW + 255) / 256, 256>>>(Wk, wkh, wkl, nW);
    split_kernel<<<(nW + 255) / 256, 256>>>(Wv, wvh, wvl, nW);
    split_kernel<<<(nW + 255) / 256, 256>>>(Wo, woh, wol, nW);

    // Q/K/V projections (tensor cores, cp.async pipeline)
    {
        dim3 gq(H_ / 128, (B_ * S_) / 128);   // (16, 64)
        gemm_cp3_nt_bias<<<gq, 256, GEMM_SMEM_BYTES>>>(hsh, hsl, wqh, wql, bq, Qp);
        dim3 gk(H_ / 128, (B_ * T_) / 128);   // (16, 8)
        gemm_cp3_nt_bias<<<gk, 256, GEMM_SMEM_BYTES>>>(ath, atl, wkh, wkl, bk, Kp);
        gemm_cp3_nt_bias<<<gk, 256, GEMM_SMEM_BYTES>>>(ath, atl, wvh, wvl, bv, Vp);
    }

    // Attention (reads g_Q, g_K, g_V -> writes g_ctx)
    {
        dim3 grid(S_ / 64, B_ * NH_);
        dim3 block(32, 8);
        attn_kernel<<<grid, block, ATTN_SMEM_BYTES>>>(mask);
    }

    // Output projection: split ctx (reuse hs split buffers), delta -> g_Q
    split_kernel<<<(nHS + 255) / 256, 256>>>(Cp, hsh, hsl, nHS);
    {
        dim3 go(H_ / 128, (B_ * S_) / 128);
        gemm_cp3_nt_bias<<<go, 256, GEMM_SMEM_BYTES>>>(hsh, hsl, woh, wol, bo, Qp);
    }

    // Scale + LayerNorm -> output
    ln_kernel<<<B_ * S_, 256>>>(Qp, rsp, gamma, beta, out);
}

// round 8
// speedup vs baseline: 2.9305x; 1.4073x over previous
#include <cuda_runtime.h>
#include <cuda_fp16.h>
#include <math.h>
#include <stdint.h>

#define B_   4
#define S_   2048
#define T_   256
#define H_   2048
#define NH_  16
#define HD_  128

// ---------------------------------------------------------------------------
// Scratch (device globals)
//   g_Q : Q output, then reused as O-projection output (delta)
//   g_hsh/g_hsl : hidden_states fp16 split, then reused as ctx split
// ---------------------------------------------------------------------------
__device__ float g_Q[B_ * S_ * H_];     // 64 MB (Q, then delta)
__device__ float g_K[B_ * T_ * H_];     //  8 MB
__device__ float g_V[B_ * T_ * H_];     //  8 MB
__device__ float g_ctx[B_ * S_ * H_];   // 64 MB

__device__ __half g_hsh[B_ * S_ * H_], g_hsl[B_ * S_ * H_];  // 32+32 MB
__device__ __half g_ath[B_ * T_ * H_], g_atl[B_ * T_ * H_];  //  4+4 MB
__device__ __half g_wq[H_ * H_];   // 8 MB each
__device__ __half g_wk[H_ * H_];
__device__ __half g_wv[H_ * H_];
__device__ __half g_wo[H_ * H_];

// ---------------------------------------------------------------------------
// Split fp32 -> fp16 hi + fp16 lo  (a = hi + lo exactly to ~22 bits)
// ---------------------------------------------------------------------------
__global__ __launch_bounds__(256) void split_f16_kernel(
    const float* __restrict__ x, __half* __restrict__ hi,
    __half* __restrict__ lo, int n4)
{
    int i = blockIdx.x * 256 + threadIdx.x;
    if (i >= n4) return;
    float4 v = reinterpret_cast<const float4*>(x)[i];
    __half h0 = __float2half(v.x), h1 = __float2half(v.y);
    __half h2 = __float2half(v.z), h3 = __float2half(v.w);
    __half2 H0 = {h0, h1}, H1 = {h2, h3};
    __half2 L0 = {__float2half(v.x - __half2float(h0)),
                  __float2half(v.y - __half2float(h1))};
    __half2 L1 = {__float2half(v.z - __half2float(h2)),
                  __float2half(v.w - __half2float(h3))};
    reinterpret_cast<__half2*>(hi)[i * 2]     = H0;
    reinterpret_cast<__half2*>(hi)[i * 2 + 1] = H1;
    reinterpret_cast<__half2*>(lo)[i * 2]     = L0;
    reinterpret_cast<__half2*>(lo)[i * 2 + 1] = L1;
}

// Convert fp32 -> fp16 (weights, single precision term)
__global__ __launch_bounds__(256) void conv_f16_kernel(
    const float* __restrict__ x, __half* __restrict__ y, int n4)
{
    int i = blockIdx.x * 256 + threadIdx.x;
    if (i >= n4) return;
    float4 v = reinterpret_cast<const float4*>(x)[i];
    __half2 Y0 = {__float2half(v.x), __float2half(v.y)};
    __half2 Y1 = {__float2half(v.z), __float2half(v.w)};
    reinterpret_cast<__half2*>(y)[i * 2]     = Y0;
    reinterpret_cast<__half2*>(y)[i * 2 + 1] = Y1;
}

// ---------------------------------------------------------------------------
// Tensor-core GEMM (mma.sync fp16, 2-term compensated):
//   C[m,n] = sum_k (Ah+Al)[m,k] * W[n,k] + bias[n],  fp32 accumulate.
// 128x128 block tile, BK=32, 256 threads (8 warps, 64x32 warp tiles).
// 3-stage cp.async pipeline; smem row stride 40 halves (80B) -> conflict-free
// LDS.32 fragment pattern (layout identical to the passing R4/R7 kernels).
// ---------------------------------------------------------------------------
#define GK       H_
#define BKq      32
#define ASTR     40
#define ARR_B    (128 * ASTR * 2)            // 10240 B per array
#define STG_B    (3 * ARR_B)                 // 30720 B per stage (Ah, Al, W)
#define NSTAGE   3
#define GEMM_SMEM_BYTES (NSTAGE * STG_B)     // 92160 B

#define CP_ASYNC16(dst, src) \
    asm volatile("cp.async.cg.shared.global [%0], [%1], 16;" \
                 :: "r"(dst), "l"(src) : "memory")
#define CP_COMMIT()  asm volatile("cp.async.commit_group;" ::: "memory")
#define CP_WAIT(N)   asm volatile("cp.async.wait_group %0;" :: "n"(N) : "memory")

#define MMA16816F(d, a, b)                                                  \
    asm volatile(                                                           \
        "mma.sync.aligned.m16n8k16.row.col.f32.f16.f16.f32 "                \
        "{%0,%1,%2,%3}, {%4,%5,%6,%7}, {%8,%9}, {%0,%1,%2,%3};"             \
        : "+f"((d)[0]), "+f"((d)[1]), "+f"((d)[2]), "+f"((d)[3])            \
        : "r"((a)[0]), "r"((a)[1]), "r"((a)[2]), "r"((a)[3]),               \
          "r"((b)[0]), "r"((b)[1]))

__device__ __forceinline__ uint32_t smem_u32g(const void* p) {
    uint32_t a;
    asm("{ .reg .u64 t; cvta.to.shared.u64 t, %1; cvt.u32.u64 %0, t; }"
        : "=r"(a) : "l"(p));
    return a;
}

__global__ __launch_bounds__(256) void gemm_f16x2_nt_bias(
    const __half* __restrict__ Ah, const __half* __restrict__ Al,
    const __half* __restrict__ W,
    const float* __restrict__ bias, float* __restrict__ C)
{
    extern __shared__ __align__(16) char smc[];
    const uint32_t sbase = smem_u32g(smc);

    const int tid  = threadIdx.x;
    const int lane = tid & 31;
    const int wid  = tid >> 5;
    const int g    = lane >> 2;       // 0..7
    const int tg   = lane & 3;        // 0..3
    const int wm   = (wid >> 2) * 64; // 0 / 64
    const int wn   = (wid & 3) * 32;  // 0,32,64,96
    const int bm   = blockIdx.y * 128;
    const int bn   = blockIdx.x * 128;

    // Loader mapping: per array 512 chunks of 16B; 2 per thread.
    uint32_t so[2];
    size_t gA[2], gB[2];
#pragma unroll
    for (int j = 0; j < 2; j++) {
        const int c  = tid + 256 * j;
        const int r  = c >> 2;
        const int cc = c & 3;
        so[j] = (uint32_t)(r * 80 + cc * 16);
        gA[j] = (size_t)(bm + r) * GK + cc * 8;
        gB[j] = (size_t)(bn + r) * GK + cc * 8;
    }

    float acc[4][4][4];
#pragma unroll
    for (int mi = 0; mi < 4; mi++)
#pragma unroll
        for (int ni = 0; ni < 4; ni++)
#pragma unroll
            for (int r = 0; r < 4; r++) acc[mi][ni][r] = 0.f;

    const int NIT = GK / BKq;  // 64

    auto issue_stage = [&](int kit, int buf) {
        const uint32_t sb = sbase + buf * STG_B;
        const int k0 = kit * BKq;
#pragma unroll
        for (int j = 0; j < 2; j++) {
            CP_ASYNC16(sb + so[j],             Ah + gA[j] + k0);
            CP_ASYNC16(sb + ARR_B + so[j],     Al + gA[j] + k0);
            CP_ASYNC16(sb + 2 * ARR_B + so[j], W  + gB[j] + k0);
        }
        CP_COMMIT();
    };

    issue_stage(0, 0);
    issue_stage(1, 1);

    for (int it = 0; it < NIT; it++) {
        if (it < NIT - 1) { CP_WAIT(1); } else { CP_WAIT(0); }
        __syncthreads();

        if (it + 2 < NIT) issue_stage(it + 2, (it + 2) % NSTAGE);

        const char* S = smc + (it % NSTAGE) * STG_B;
        const __half* SAh = reinterpret_cast<const __half*>(S);
        const __half* SAl = reinterpret_cast<const __half*>(S + ARR_B);
        const __half* SB  = reinterpret_cast<const __half*>(S + 2 * ARR_B);

#pragma unroll
        for (int ks = 0; ks < BKq; ks += 16) {
            unsigned fa_h[4][4], fa_l[4][4], fb[4][2];
#pragma unroll
            for (int mi = 0; mi < 4; mi++) {
                const int r0 = wm + mi * 16 + g;
                const int c0 = ks + 2 * tg;
                fa_h[mi][0] = *reinterpret_cast<const unsigned*>(&SAh[r0 * ASTR + c0]);
                fa_h[mi][1] = *reinterpret_cast<const unsigned*>(&SAh[(r0 + 8) * ASTR + c0]);
                fa_h[mi][2] = *reinterpret_cast<const unsigned*>(&SAh[r0 * ASTR + c0 + 8]);
                fa_h[mi][3] = *reinterpret_cast<const unsigned*>(&SAh[(r0 + 8) * ASTR + c0 + 8]);
                fa_l[mi][0] = *reinterpret_cast<const unsigned*>(&SAl[r0 * ASTR + c0]);
                fa_l[mi][1] = *reinterpret_cast<const unsigned*>(&SAl[(r0 + 8) * ASTR + c0]);
                fa_l[mi][2] = *reinterpret_cast<const unsigned*>(&SAl[r0 * ASTR + c0 + 8]);
                fa_l[mi][3] = *reinterpret_cast<const unsigned*>(&SAl[(r0 + 8) * ASTR + c0 + 8]);
            }
#pragma unroll
            for (int ni = 0; ni < 4; ni++) {
                const int n0 = wn + ni * 8 + g;
                const int c0 = ks + 2 * tg;
                fb[ni][0] = *reinterpret_cast<const unsigned*>(&SB[n0 * ASTR + c0]);
                fb[ni][1] = *reinterpret_cast<const unsigned*>(&SB[n0 * ASTR + c0 + 8]);
            }
#pragma unroll
            for (int mi = 0; mi < 4; mi++)
#pragma unroll
                for (int ni = 0; ni < 4; ni++) {
                    MMA16816F(acc[mi][ni], fa_h[mi], fb[ni]);
                    MMA16816F(acc[mi][ni], fa_l[mi], fb[ni]);
                }
        }
    }

    // Epilogue: bias add, fp32 stores
#pragma unroll
    for (int mi = 0; mi < 4; mi++) {
        const int r0 = bm + wm + mi * 16 + g;
#pragma unroll
        for (int ni = 0; ni < 4; ni++) {
            const int c0 = bn + wn + ni * 8 + 2 * tg;
            const float b0 = bias[c0], b1 = bias[c0 + 1];
            float2 v0 = make_float2(acc[mi][ni][0] + b0, acc[mi][ni][1] + b1);
            float2 v1 = make_float2(acc[mi][ni][2] + b0, acc[mi][ni][3] + b1);
            *reinterpret_cast<float2*>(C + (size_t)r0 * H_ + c0)       = v0;
            *reinterpret_cast<float2*>(C + (size_t)(r0 + 8) * H_ + c0) = v1;
        }
    }
}

// ---------------------------------------------------------------------------
// Attention (unchanged from passing R7 kernel)
// ---------------------------------------------------------------------------
#define PS_STRIDE 260
#define ATTN_SMEM_FLOATS (5120 + 64 * PS_STRIDE)
#define ATTN_SMEM_BYTES  (ATTN_SMEM_FLOATS * 4)

__global__ __launch_bounds__(256) void attn_kernel(const int* __restrict__ mask)
{
    extern __shared__ __align__(16) float smf[];
    float* As = smf;
    float* Ks = smf + 1024;
    float* Ps = smf + 5120;
    float* Vs = smf;

    const int tx  = threadIdx.x;
    const int ty  = threadIdx.y;
    const int tid = ty * 32 + tx;
    const int b   = blockIdx.y >> 4;
    const int h   = blockIdx.y & 15;
    const int s0  = blockIdx.x * 64;

    const float* Qb = g_Q + (size_t)(b * S_ + s0) * H_ + h * HD_;
    const float* Kb = g_K + (size_t)b * T_ * H_ + h * HD_;
    const float* Vb = g_V + (size_t)b * T_ * H_ + h * HD_;

    bool am[8];
#pragma unroll
    for (int j = 0; j < 8; j++) am[j] = mask[b * T_ + tx * 8 + j] > 0;

    float acc[8][8];
#pragma unroll
    for (int i = 0; i < 8; i++)
#pragma unroll
        for (int j = 0; j < 8; j++) acc[i][j] = 0.f;

    const int qrow = tid >> 2;
    const int qc   = (tid & 3) * 4;

    for (int kc = 0; kc < 8; kc++) {
        const int d0 = kc * 16;
        float4 qv = *reinterpret_cast<const float4*>(Qb + (size_t)qrow * H_ + d0 + qc);
        float4 kv[4];
#pragma unroll
        for (int r = 0; r < 4; r++) {
            const int t = (tid >> 2) + 64 * r;
            kv[r] = *reinterpret_cast<const float4*>(Kb + (size_t)t * H_ + d0 + qc);
        }
        __syncthreads();
        As[(qc + 0) * 64 + qrow] = qv.x;
        As[(qc + 1) * 64 + qrow] = qv.y;
        As[(qc + 2) * 64 + qrow] = qv.z;
        As[(qc + 3) * 64 + qrow] = qv.w;
#pragma unroll
        for (int r = 0; r < 4; r++) {
            const int t = (tid >> 2) + 64 * r;
            Ks[(qc + 0) * 256 + t] = kv[r].x;
            Ks[(qc + 1) * 256 + t] = kv[r].y;
            Ks[(qc + 2) * 256 + t] = kv[r].z;
            Ks[(qc + 3) * 256 + t] = kv[r].w;
        }
        __syncthreads();
#pragma unroll
        for (int dd = 0; dd < 16; dd++) {
            float4 a0 = *reinterpret_cast<const float4*>(&As[dd * 64 + ty * 8]);
            float4 a1 = *reinterpret_cast<const float4*>(&As[dd * 64 + ty * 8 + 4]);
            float4 b0 = *reinterpret_cast<const float4*>(&Ks[dd * 256 + tx * 8]);
            float4 b1 = *reinterpret_cast<const float4*>(&Ks[dd * 256 + tx * 8 + 4]);
            float ar[8] = {a0.x, a0.y, a0.z, a0.w, a1.x, a1.y, a1.z, a1.w};
            float br[8] = {b0.x, b0.y, b0.z, b0.w, b1.x, b1.y, b1.z, b1.w};
#pragma unroll
            for (int i = 0; i < 8; i++)
#pragma unroll
                for (int j = 0; j < 8; j++)
                    acc[i][j] += ar[i] * br[j];
        }
    }

    const float scale = 0.08838834764831845f;
#pragma unroll
    for (int i = 0; i < 8; i++) {
        float mx = -60.f;
#pragma unroll
        for (int j = 0; j < 8; j++) {
            float s = acc[i][j] * scale;
            s = fminf(fmaxf(s, -50.f), 50.f);
            if (!am[j]) s = -50.f;
            acc[i][j] = s;
            mx = fmaxf(mx, s);
        }
#pragma unroll
        for (int o = 16; o; o >>= 1) mx = fmaxf(mx, __shfl_xor_sync(0xffffffffu, mx, o));
        float se = 0.f;
#pragma unroll
        for (int j = 0; j < 8; j++) { acc[i][j] = __expf(acc[i][j] - mx); se += acc[i][j]; }
#pragma unroll
        for (int o = 16; o; o >>= 1) se += __shfl_xor_sync(0xffffffffu, se, o);
        const float inv = 1.f / se;
#pragma unroll
        for (int j = 0; j < 8; j++)
            Ps[(ty * 8 + i) * PS_STRIDE + tx * 8 + j] = acc[i][j] * inv;
    }
    __syncthreads();

    float c2[8][4];
#pragma unroll
    for (int i = 0; i < 8; i++)
#pragma unroll
        for (int j = 0; j < 4; j++) c2[i][j] = 0.f;

    for (int tc = 0; tc < 8; tc++) {
        const int t0 = tc * 32;
        float4 vv[4];
#pragma unroll
        for (int r = 0; r < 4; r++) {
            const int idx = tid + r * 256;
            const int vr = idx >> 5;
            const int vc = (idx & 31) * 4;
            vv[r] = *reinterpret_cast<const float4*>(Vb + (size_t)(t0 + vr) * H_ + vc);
        }
        __syncthreads();
#pragma unroll
        for (int r = 0; r < 4; r++) {
            const int idx = tid + r * 256;
            const int vr = idx >> 5;
            const int vc = (idx & 31) * 4;
            *reinterpret_cast<float4*>(&Vs[vr * 128 + vc]) = vv[r];
        }
        __syncthreads();
#pragma unroll
        for (int tt = 0; tt < 32; tt++) {
            float4 v = *reinterpret_cast<const float4*>(&Vs[tt * 128 + tx * 4]);
#pragma unroll
            for (int i = 0; i < 8; i++) {
                const float p = Ps[(ty * 8 + i) * PS_STRIDE + t0 + tt];
                c2[i][0] += p * v.x;
                c2[i][1] += p * v.y;
                c2[i][2] += p * v.z;
                c2[i][3] += p * v.w;
            }
        }
    }

#pragma unroll
    for (int i = 0; i < 8; i++) {
        float* o = g_ctx + (size_t)(b * S_ + s0 + ty * 8 + i) * H_ + h * HD_ + tx * 4;
        float4 w = make_float4(c2[i][0], c2[i][1], c2[i][2], c2[i][3]);
        *reinterpret_cast<float4*>(o) = w;
    }
}

// ---------------------------------------------------------------------------
// LayerNorm (unchanged)
// ---------------------------------------------------------------------------
__device__ __forceinline__ float block_sum256(float val, float* red)
{
#pragma unroll
    for (int o = 16; o; o >>= 1) val += __shfl_xor_sync(0xffffffffu, val, o);
    if ((threadIdx.x & 31) == 0) red[threadIdx.x >> 5] = val;
    __syncthreads();
    float tot = red[0] + red[1] + red[2] + red[3] + red[4] + red[5] + red[6] + red[7];
    __syncthreads();
    return tot;
}

__global__ __launch_bounds__(256) void ln_kernel(
    const float* __restrict__ delta, const float* __restrict__ rsp,
    const float* __restrict__ gamma, const float* __restrict__ beta,
    float* __restrict__ out)
{
    __shared__ float red[8];
    const int row = blockIdx.x;
    const int tid = threadIdx.x;
    const float rs = fminf(fmaxf(rsp[0], 0.f), 0.3f);
    const float* x = delta + (size_t)row * H_;

    float v[8];
    float s = 0.f;
#pragma unroll
    for (int k = 0; k < 8; k++) { v[k] = rs * x[tid + 256 * k]; s += v[k]; }
    const float mean = block_sum256(s, red) * (1.f / H_);

    float sq = 0.f;
#pragma unroll
    for (int k = 0; k < 8; k++) { float d = v[k] - mean; sq += d * d; }
    const float var = block_sum256(sq, red) * (1.f / H_);
    const float inv = rsqrtf(var + 1e-5f);

#pragma unroll
    for (int k = 0; k < 8; k++) {
        const int c = tid + 256 * k;
        out[(size_t)row * H_ + c] = (v[k] - mean) * inv * gamma[c] + beta[c];
    }
}

// ---------------------------------------------------------------------------
// Launch
// ---------------------------------------------------------------------------
extern "C" void kernel_launch(void* const* d_in, const int* in_sizes, int n_in,
                              void* d_out, int out_size)
{
    const float* hs    = (const float*)d_in[0];
    const float* at    = (const float*)d_in[1];
    const int*   mask  = (const int*)  d_in[2];
    const float* Wq    = (const float*)d_in[3];
    const float* bq    = (const float*)d_in[4];
    const float* Wk    = (const float*)d_in[5];
    const float* bk    = (const float*)d_in[6];
    const float* Wv    = (const float*)d_in[7];
    const float* bv    = (const float*)d_in[8];
    const float* Wo    = (const float*)d_in[9];
    const float* bo    = (const float*)d_in[10];
    const float* gamma = (const float*)d_in[11];
    const float* beta  = (const float*)d_in[12];
    const float* rsp   = (const float*)d_in[13];
    float* out = (float*)d_out;

    float *Qp, *Kp, *Vp, *Cp;
    __half *hsh, *hsl, *ath, *atl, *wq, *wk, *wv, *wo;
    cudaGetSymbolAddress((void**)&Qp,  g_Q);
    cudaGetSymbolAddress((void**)&Kp,  g_K);
    cudaGetSymbolAddress((void**)&Vp,  g_V);
    cudaGetSymbolAddress((void**)&Cp,  g_ctx);
    cudaGetSymbolAddress((void**)&hsh, g_hsh); cudaGetSymbolAddress((void**)&hsl, g_hsl);
    cudaGetSymbolAddress((void**)&ath, g_ath); cudaGetSymbolAddress((void**)&atl, g_atl);
    cudaGetSymbolAddress((void**)&wq,  g_wq);
    cudaGetSymbolAddress((void**)&wk,  g_wk);
    cudaGetSymbolAddress((void**)&wv,  g_wv);
    cudaGetSymbolAddress((void**)&wo,  g_wo);

    cudaFuncSetAttribute(attn_kernel, cudaFuncAttributeMaxDynamicSharedMemorySize,
                         ATTN_SMEM_BYTES);
    cudaFuncSetAttribute(gemm_f16x2_nt_bias, cudaFuncAttributeMaxDynamicSharedMemorySize,
                         GEMM_SMEM_BYTES);

    // Splits / conversions
    const int nHS = B_ * S_ * H_ / 4, nAT = B_ * T_ * H_ / 4, nW = H_ * H_ / 4;
    split_f16_kernel<<<(nHS + 255) / 256, 256>>>(hs, hsh, hsl, nHS);
    split_f16_kernel<<<(nAT + 255) / 256, 256>>>(at, ath, atl, nAT);
    conv_f16_kernel<<<(nW + 255) / 256, 256>>>(Wq, wq, nW);
    conv_f16_kernel<<<(nW + 255) / 256, 256>>>(Wk, wk, nW);
    conv_f16_kernel<<<(nW + 255) / 256, 256>>>(Wv, wv, nW);
    conv_f16_kernel<<<(nW + 255) / 256, 256>>>(Wo, wo, nW);

    // Q/K/V projections (tensor cores, 2-term fp16)
    {
        dim3 gq(H_ / 128, (B_ * S_) / 128);   // (16, 64)
        gemm_f16x2_nt_bias<<<gq, 256, GEMM_SMEM_BYTES>>>(hsh, hsl, wq, bq, Qp);
        dim3 gk(H_ / 128, (B_ * T_) / 128);   // (16, 8)
        gemm_f16x2_nt_bias<<<gk, 256, GEMM_SMEM_BYTES>>>(ath, atl, wk, bk, Kp);
        gemm_f16x2_nt_bias<<<gk, 256, GEMM_SMEM_BYTES>>>(ath, atl, wv, bv, Vp);
    }

    // Attention (reads g_Q, g_K, g_V -> writes g_ctx)
    {
        dim3 grid(S_ / 64, B_ * NH_);
        dim3 block(32, 8);
        attn_kernel<<<grid, block, ATTN_SMEM_BYTES>>>(mask);
    }

    // Output projection: split ctx (reuse hs split buffers), delta -> g_Q
    split_f16_kernel<<<(nHS + 255) / 256, 256>>>(Cp, hsh, hsl, nHS);
    {
        dim3 go(H_ / 128, (B_ * S_) / 128);
        gemm_f16x2_nt_bias<<<go, 256, GEMM_SMEM_BYTES>>>(hsh, hsl, wo, bo, Qp);
    }

    // Scale + LayerNorm -> output
    ln_kernel<<<B_ * S_, 256>>>(Qp, rsp, gamma, beta, out);
}